// round 9
// baseline (speedup 1.0000x reference)
#include <cuda_runtime.h>
#include <cuda_fp16.h>

#define NN 100000
#define EE 3200000
#define GG 100
#define FI 16
#define HH 48

// ---------------- device scratch ----------------
__device__ float g_T1[NN * HH];
__device__ float g_T2[NN * HH];
__device__ float g_T3[NN * HH];
__device__ float g_T4[NN * HH];
__device__ float g_H [NN * HH];
__device__ __half g_H16 [NN * HH];
__device__ __half g_T116[NN * HH];
__device__ __half g_T216[NN * HH];
__device__ __half g_T316[NN * HH];
__device__ float g_dis[NN];
__device__ float g_diag[NN];
__device__ int   g_outc[NN];
__device__ int   g_inc[NN];
__device__ int   g_fill[NN];
__device__ int   g_rowptr[NN + 1];
__device__ int2  g_edge[EE];          // {src, weight-as-int}
__device__ float g_pool[GG * HH];

// ---------------- CSR build ----------------
__global__ void deg_k(const int* __restrict__ ei) {
    int e = blockIdx.x * blockDim.x + threadIdx.x;
    if (e >= EE) return;
    atomicAdd(&g_outc[ei[e]], 1);
    atomicAdd(&g_inc[ei[EE + e]], 1);
}

__global__ void scan_k() {
    __shared__ int ssum[1024];
    const int t = threadIdx.x;
    const int chunk = 98;
    int start = t * chunk;
    int end = start + chunk; if (end > NN) end = NN;
    int s = 0;
    for (int i = start; i < end; ++i) s += g_inc[i];
    ssum[t] = s;
    __syncthreads();
    for (int off = 1; off < 1024; off <<= 1) {
        int v = (t >= off) ? ssum[t - off] : 0;
        __syncthreads();
        ssum[t] += v;
        __syncthreads();
    }
    int run = (t == 0) ? 0 : ssum[t - 1];
    for (int i = start; i < end; ++i) { g_rowptr[i] = run; run += g_inc[i]; }
    if (t == 1023) g_rowptr[NN] = run;
}

__global__ void nodeinit_k(const int* __restrict__ batch, const float* __restrict__ lmax) {
    int n = blockIdx.x * blockDim.x + threadIdx.x;
    if (n >= NN) return;
    int dg = g_outc[n];
    g_dis[n]  = (dg > 0) ? rsqrtf((float)dg) : 0.f;
    g_diag[n] = 2.f / lmax[batch[n]] - 1.f;
}

__global__ void wedge_k(const int* __restrict__ ei, const int* __restrict__ batch,
                        const float* __restrict__ lmax) {
    int e = blockIdx.x * blockDim.x + threadIdx.x;
    if (e >= EE) return;
    int s = ei[e];
    int d = ei[EE + e];
    float w = -2.f * g_dis[s] * g_dis[d] / lmax[batch[s]];
    int pos = g_rowptr[d] + atomicAdd(&g_fill[d], 1);
    g_edge[pos] = make_int2(s, __float_as_int(w));
}

// ---------------- prop, F=48: fp16 neighbor gather, fp32 master ----------------
// mode=0: Tn = diag*Tc + gather      (T1)
// mode=1: Tn = 2*(diag*Tc + gather) - Tp
__global__ __launch_bounds__(256, 2)
void prop48_k(const float* __restrict__ Tc, const uint4* __restrict__ Tc16,
              const float* __restrict__ Tp, float* __restrict__ Tn,
              uint4* __restrict__ Tn16, int mode, int w16) {
    int n = blockIdx.x * blockDim.x + threadIdx.x;
    if (n >= NN) return;
    float acc[48];
    float dg = g_diag[n];
    const float4* crow = reinterpret_cast<const float4*>(Tc + n * 48);
#pragma unroll
    for (int c = 0; c < 12; ++c) {
        float4 v = __ldg(&crow[c]);
        acc[4*c+0] = dg * v.x; acc[4*c+1] = dg * v.y;
        acc[4*c+2] = dg * v.z; acc[4*c+3] = dg * v.w;
    }
    const int e1 = g_rowptr[n + 1];
    for (int j = g_rowptr[n]; j < e1; ++j) {
        int2 e = __ldg(&g_edge[j]);
        float w = __int_as_float(e.y);
        const uint4* u = Tc16 + (size_t)e.x * 6;   // 6 x uint4 = 48 halves
#pragma unroll
        for (int c = 0; c < 6; ++c) {
            uint4 q = __ldg(&u[c]);
            float2 f0 = __half22float2(*reinterpret_cast<const __half2*>(&q.x));
            float2 f1 = __half22float2(*reinterpret_cast<const __half2*>(&q.y));
            float2 f2 = __half22float2(*reinterpret_cast<const __half2*>(&q.z));
            float2 f3 = __half22float2(*reinterpret_cast<const __half2*>(&q.w));
            acc[8*c+0] += w * f0.x; acc[8*c+1] += w * f0.y;
            acc[8*c+2] += w * f1.x; acc[8*c+3] += w * f1.y;
            acc[8*c+4] += w * f2.x; acc[8*c+5] += w * f2.y;
            acc[8*c+6] += w * f3.x; acc[8*c+7] += w * f3.y;
        }
    }
    if (mode) {
        const float4* prow = reinterpret_cast<const float4*>(Tp + n * 48);
#pragma unroll
        for (int c = 0; c < 12; ++c) {
            float4 p = __ldg(&prow[c]);
            acc[4*c+0] = 2.f * acc[4*c+0] - p.x;
            acc[4*c+1] = 2.f * acc[4*c+1] - p.y;
            acc[4*c+2] = 2.f * acc[4*c+2] - p.z;
            acc[4*c+3] = 2.f * acc[4*c+3] - p.w;
        }
    }
    float4* orow = reinterpret_cast<float4*>(Tn + n * 48);
#pragma unroll
    for (int c = 0; c < 12; ++c)
        orow[c] = make_float4(acc[4*c+0], acc[4*c+1], acc[4*c+2], acc[4*c+3]);
    if (w16) {
        uint4* hrow = Tn16 + (size_t)n * 6;
#pragma unroll
        for (int c = 0; c < 6; ++c) {
            __half2 h0 = __float22half2_rn(make_float2(acc[8*c+0], acc[8*c+1]));
            __half2 h1 = __float22half2_rn(make_float2(acc[8*c+2], acc[8*c+3]));
            __half2 h2 = __float22half2_rn(make_float2(acc[8*c+4], acc[8*c+5]));
            __half2 h3 = __float22half2_rn(make_float2(acc[8*c+6], acc[8*c+7]));
            uint4 q;
            q.x = *reinterpret_cast<unsigned*>(&h0);
            q.y = *reinterpret_cast<unsigned*>(&h1);
            q.z = *reinterpret_cast<unsigned*>(&h2);
            q.w = *reinterpret_cast<unsigned*>(&h3);
            hrow[c] = q;
        }
    }
}

// ---------------- prop, F=16: fp32 gather (layer 1) ----------------
__global__ __launch_bounds__(256, 2)
void prop16_k(const float* __restrict__ Tc, const float* __restrict__ Tp,
              float* __restrict__ Tn, int mode) {
    int n = blockIdx.x * blockDim.x + threadIdx.x;
    if (n >= NN) return;
    float acc[16];
    float dg = g_diag[n];
    const float4* crow = reinterpret_cast<const float4*>(Tc + n * 16);
#pragma unroll
    for (int c = 0; c < 4; ++c) {
        float4 v = __ldg(&crow[c]);
        acc[4*c+0] = dg * v.x; acc[4*c+1] = dg * v.y;
        acc[4*c+2] = dg * v.z; acc[4*c+3] = dg * v.w;
    }
    const int e1 = g_rowptr[n + 1];
    for (int j = g_rowptr[n]; j < e1; ++j) {
        int2 e = __ldg(&g_edge[j]);
        float w = __int_as_float(e.y);
        const float4* u = reinterpret_cast<const float4*>(Tc + (size_t)e.x * 16);
#pragma unroll
        for (int c = 0; c < 4; ++c) {
            float4 q = __ldg(&u[c]);
            acc[4*c+0] += w * q.x; acc[4*c+1] += w * q.y;
            acc[4*c+2] += w * q.z; acc[4*c+3] += w * q.w;
        }
    }
    if (mode) {
        const float4* prow = reinterpret_cast<const float4*>(Tp + n * 16);
#pragma unroll
        for (int c = 0; c < 4; ++c) {
            float4 p = __ldg(&prow[c]);
            acc[4*c+0] = 2.f * acc[4*c+0] - p.x;
            acc[4*c+1] = 2.f * acc[4*c+1] - p.y;
            acc[4*c+2] = 2.f * acc[4*c+2] - p.z;
            acc[4*c+3] = 2.f * acc[4*c+3] - p.w;
        }
    }
    float4* orow = reinterpret_cast<float4*>(Tn + n * 16);
#pragma unroll
    for (int c = 0; c < 4; ++c)
        orow[c] = make_float4(acc[4*c+0], acc[4*c+1], acc[4*c+2], acc[4*c+3]);
}

// ---------------- per-layer GEMM: H' = relu(sum_k T_k @ W[k] + b) ----------------
// tile: 256 nodes x 48 h, threads (32,6), thread = 8 nodes (stride 32) x 8 h
template <int F>
__device__ __forceinline__ void gemm_phase(const float* __restrict__ Tk,
                                           const float* __restrict__ Wsk,
                                           float* __restrict__ Ts,
                                           float acc[8][8], int n0, int tx, int ty, int tid) {
    const int PITCH = F + 1;
    __syncthreads();
    for (int idx = tid; idx < 256 * F; idx += 192) {
        int node = idx / F, f = idx - node * F;
        int gn = n0 + node;
        Ts[node * PITCH + f] = (gn < NN) ? Tk[(size_t)gn * F + f] : 0.f;
    }
    __syncthreads();
#pragma unroll 4
    for (int f = 0; f < F; ++f) {
        float4 w0 = *reinterpret_cast<const float4*>(&Wsk[f * 48 + ty * 8]);
        float4 w1 = *reinterpret_cast<const float4*>(&Wsk[f * 48 + ty * 8 + 4]);
#pragma unroll
        for (int i = 0; i < 8; ++i) {
            float t = Ts[(tx + 32 * i) * PITCH + f];
            acc[i][0] += t * w0.x; acc[i][1] += t * w0.y;
            acc[i][2] += t * w0.z; acc[i][3] += t * w0.w;
            acc[i][4] += t * w1.x; acc[i][5] += t * w1.y;
            acc[i][6] += t * w1.z; acc[i][7] += t * w1.w;
        }
    }
}

template <int F>
__global__ __launch_bounds__(192, 2)
void gemm5_k(const float* __restrict__ T0, const float* __restrict__ T1,
             const float* __restrict__ T2, const float* __restrict__ T3,
             const float* __restrict__ T4,
             const float* __restrict__ W, const float* __restrict__ bias,
             float* __restrict__ OUT, uint4* __restrict__ OUT16, int w16) {
    extern __shared__ float smem[];
    float* Ws = smem;                       // 5*F*48
    float* Ts = smem + 5 * F * 48;          // 256*(F+1)
    const int tx = threadIdx.x, ty = threadIdx.y;
    const int tid = ty * 32 + tx;
    const int n0 = blockIdx.x * 256;
    for (int i = tid; i < 5 * F * 48; i += 192) Ws[i] = W[i];
    float acc[8][8];
#pragma unroll
    for (int i = 0; i < 8; ++i)
#pragma unroll
        for (int j = 0; j < 8; ++j) acc[i][j] = 0.f;

    gemm_phase<F>(T0, Ws + 0 * F * 48, Ts, acc, n0, tx, ty, tid);
    gemm_phase<F>(T1, Ws + 1 * F * 48, Ts, acc, n0, tx, ty, tid);
    gemm_phase<F>(T2, Ws + 2 * F * 48, Ts, acc, n0, tx, ty, tid);
    gemm_phase<F>(T3, Ws + 3 * F * 48, Ts, acc, n0, tx, ty, tid);
    gemm_phase<F>(T4, Ws + 4 * F * 48, Ts, acc, n0, tx, ty, tid);

    float b[8];
#pragma unroll
    for (int j = 0; j < 8; ++j) b[j] = bias[ty * 8 + j];
#pragma unroll
    for (int i = 0; i < 8; ++i) {
        int n = n0 + tx + 32 * i;
        if (n >= NN) continue;
        float r[8];
#pragma unroll
        for (int j = 0; j < 8; ++j) r[j] = fmaxf(acc[i][j] + b[j], 0.f);
        float4* o = reinterpret_cast<float4*>(OUT + (size_t)n * 48 + ty * 8);
        o[0] = make_float4(r[0], r[1], r[2], r[3]);
        o[1] = make_float4(r[4], r[5], r[6], r[7]);
        if (w16) {
            __half2 h0 = __float22half2_rn(make_float2(r[0], r[1]));
            __half2 h1 = __float22half2_rn(make_float2(r[2], r[3]));
            __half2 h2 = __float22half2_rn(make_float2(r[4], r[5]));
            __half2 h3 = __float22half2_rn(make_float2(r[6], r[7]));
            uint4 q;
            q.x = *reinterpret_cast<unsigned*>(&h0);
            q.y = *reinterpret_cast<unsigned*>(&h1);
            q.z = *reinterpret_cast<unsigned*>(&h2);
            q.w = *reinterpret_cast<unsigned*>(&h3);
            // each thread owns 8 halves = 16B = one uint4; row = 6 uint4 slots
            OUT16[(size_t)n * 6 + ty] = q;
        }
    }
}

// ---------------- pooling ----------------
__global__ void pool_k(const float* __restrict__ Hin) {
    __shared__ float red[8][48];
    const int g = blockIdx.x;
    const int h = threadIdx.x;
    const int y = threadIdx.y;
    const float* base = Hin + (size_t)g * 1000 * 48;
    float s = 0.f;
    for (int i = y; i < 1000; i += 8) s += base[i * 48 + h];
    red[y][h] = s;
    __syncthreads();
    if (y == 0) {
        float t = 0.f;
#pragma unroll
        for (int q = 0; q < 8; ++q) t += red[q][h];
        g_pool[g * 48 + h] = t;
    }
}

__global__ void mlp_k(const float* __restrict__ fc1w, const float* __restrict__ fc1b,
                      const float* __restrict__ fc2w, const float* __restrict__ fc2b,
                      float* __restrict__ out) {
    const int g = blockIdx.x;
    const int j = threadIdx.x;
    float a = fc1b[j];
#pragma unroll
    for (int f = 0; f < 48; ++f) a += g_pool[g * 48 + f] * fc1w[f * 32 + j];
    a = fmaxf(a, 0.f);
    float v = a * fc2w[j];
#pragma unroll
    for (int off = 16; off; off >>= 1) v += __shfl_down_sync(0xffffffffu, v, off);
    if (j == 0) out[g] = v + fc2b[0];
}

extern "C" void kernel_launch(void* const* d_in, const int* in_sizes, int n_in,
                              void* d_out, int out_size) {
    (void)in_sizes; (void)n_in; (void)out_size;
    const float* x     = (const float*)d_in[0];
    const int*   ei    = (const int*)  d_in[1];
    const int*   batch = (const int*)  d_in[2];
    const float* lmax  = (const float*)d_in[3];
    const float* W1 = (const float*)d_in[4];  const float* b1 = (const float*)d_in[5];
    const float* W2 = (const float*)d_in[6];  const float* b2 = (const float*)d_in[7];
    const float* W3 = (const float*)d_in[8];  const float* b3 = (const float*)d_in[9];
    const float* W4 = (const float*)d_in[10]; const float* b4 = (const float*)d_in[11];
    const float* W5 = (const float*)d_in[12]; const float* b5 = (const float*)d_in[13];
    const float* fc1w = (const float*)d_in[14]; const float* fc1b = (const float*)d_in[15];
    const float* fc2w = (const float*)d_in[16]; const float* fc2b = (const float*)d_in[17];
    float* out = (float*)d_out;

    void* p;
    cudaGetSymbolAddress(&p, g_T1);   float* T1 = (float*)p;
    cudaGetSymbolAddress(&p, g_T2);   float* T2 = (float*)p;
    cudaGetSymbolAddress(&p, g_T3);   float* T3 = (float*)p;
    cudaGetSymbolAddress(&p, g_T4);   float* T4 = (float*)p;
    cudaGetSymbolAddress(&p, g_H);    float* Hb = (float*)p;
    cudaGetSymbolAddress(&p, g_H16);  uint4* H16 = (uint4*)p;
    cudaGetSymbolAddress(&p, g_T116); uint4* T116 = (uint4*)p;
    cudaGetSymbolAddress(&p, g_T216); uint4* T216 = (uint4*)p;
    cudaGetSymbolAddress(&p, g_T316); uint4* T316 = (uint4*)p;
    cudaGetSymbolAddress(&p, g_outc); void* outc_p = p;
    cudaGetSymbolAddress(&p, g_inc);  void* inc_p  = p;
    cudaGetSymbolAddress(&p, g_fill); void* fill_p = p;

    cudaMemsetAsync(outc_p, 0, NN * sizeof(int));
    cudaMemsetAsync(inc_p,  0, NN * sizeof(int));
    cudaMemsetAsync(fill_p, 0, NN * sizeof(int));

    const int EB = (EE + 255) / 256;
    const int NB = (NN + 255) / 256;
    deg_k<<<EB, 256>>>(ei);
    scan_k<<<1, 1024>>>();
    nodeinit_k<<<NB, 256>>>(batch, lmax);
    wedge_k<<<EB, 256>>>(ei, batch, lmax);

    // shared mem sizes (dynamic; opt in above 48KB default — idempotent host call)
    const int smem48 = (5 * 48 * 48 + 256 * 49) * sizeof(float);
    const int smem16 = (5 * 16 * 48 + 256 * 17) * sizeof(float);
    cudaFuncSetAttribute(gemm5_k<48>, cudaFuncAttributeMaxDynamicSharedMemorySize, smem48);
    cudaFuncSetAttribute(gemm5_k<16>, cudaFuncAttributeMaxDynamicSharedMemorySize, smem16);

    const int GB = (NN + 255) / 256;
    dim3 gt(32, 6);

    // ---- layer 1 (F=16, fp32 gather) ----
    prop16_k<<<NB, 256>>>(x,  nullptr, T1, 0);
    prop16_k<<<NB, 256>>>(T1, x,       T2, 1);
    prop16_k<<<NB, 256>>>(T2, T1,      T3, 1);
    prop16_k<<<NB, 256>>>(T3, T2,      T4, 1);
    gemm5_k<16><<<GB, gt, smem16>>>(x, T1, T2, T3, T4, W1, b1, Hb, H16, 1);

    // ---- layers 2..5 (F=48, fp16 gather) ----
    const float* Ws[4] = {W2, W3, W4, W5};
    const float* bs[4] = {b2, b3, b4, b5};
    for (int L = 0; L < 4; ++L) {
        prop48_k<<<NB, 256>>>(Hb, H16,  nullptr, T1, T116, 0, 1);
        prop48_k<<<NB, 256>>>(T1, T116, Hb,      T2, T216, 1, 1);
        prop48_k<<<NB, 256>>>(T2, T216, T1,      T3, T316, 1, 1);
        prop48_k<<<NB, 256>>>(T3, T316, T2,      T4, nullptr, 1, 0);
        int last = (L == 3);
        gemm5_k<48><<<GB, gt, smem48>>>(Hb, T1, T2, T3, T4, Ws[L], bs[L], Hb, H16, last ? 0 : 1);
    }

    pool_k<<<GG, dim3(48, 8)>>>(Hb);
    mlp_k<<<GG, 32>>>(fc1w, fc1b, fc2w, fc2b, out);
}

// round 12
// speedup vs baseline: 1.6166x; 1.6166x over previous
#include <cuda_runtime.h>
#include <cuda_fp16.h>

#define NN 100000
#define EE 3200000
#define GG 100
#define FI 16
#define HH 48

// ---------------- device scratch ----------------
__device__ float g_T1[NN * HH];
__device__ float g_T2[NN * HH];
__device__ float g_T3[NN * HH];
__device__ float g_T4[NN * HH];
__device__ float g_H [NN * HH];
__device__ __half g_H16 [NN * HH];
__device__ __half g_T116[NN * HH];
__device__ __half g_T216[NN * HH];
__device__ __half g_T316[NN * HH];
__device__ float g_dis[NN];
__device__ float g_diag[NN];
__device__ int   g_outc[NN];
__device__ int   g_inc[NN];
__device__ int   g_fill[NN];
__device__ int   g_rowptr[NN + 1];
__device__ int2  g_edge[EE];          // {src, weight-as-int}
__device__ float g_pool[GG * HH];

// ---------------- CSR build ----------------
__global__ void deg_k(const int* __restrict__ ei) {
    int e = blockIdx.x * blockDim.x + threadIdx.x;
    if (e >= EE) return;
    atomicAdd(&g_outc[ei[e]], 1);
    atomicAdd(&g_inc[ei[EE + e]], 1);
}

__global__ void scan_k() {
    __shared__ int ssum[1024];
    const int t = threadIdx.x;
    const int chunk = 98;
    int start = t * chunk;
    int end = start + chunk; if (end > NN) end = NN;
    int s = 0;
    for (int i = start; i < end; ++i) s += g_inc[i];
    ssum[t] = s;
    __syncthreads();
    for (int off = 1; off < 1024; off <<= 1) {
        int v = (t >= off) ? ssum[t - off] : 0;
        __syncthreads();
        ssum[t] += v;
        __syncthreads();
    }
    int run = (t == 0) ? 0 : ssum[t - 1];
    for (int i = start; i < end; ++i) { g_rowptr[i] = run; run += g_inc[i]; }
    if (t == 1023) g_rowptr[NN] = run;
}

__global__ void nodeinit_k(const int* __restrict__ batch, const float* __restrict__ lmax) {
    int n = blockIdx.x * blockDim.x + threadIdx.x;
    if (n >= NN) return;
    int dg = g_outc[n];
    g_dis[n]  = (dg > 0) ? rsqrtf((float)dg) : 0.f;
    g_diag[n] = 2.f / lmax[batch[n]] - 1.f;
}

__global__ void wedge_k(const int* __restrict__ ei, const int* __restrict__ batch,
                        const float* __restrict__ lmax) {
    int e = blockIdx.x * blockDim.x + threadIdx.x;
    if (e >= EE) return;
    int s = ei[e];
    int d = ei[EE + e];
    float w = -2.f * g_dis[s] * g_dis[d] / lmax[batch[s]];
    int pos = g_rowptr[d] + atomicAdd(&g_fill[d], 1);
    g_edge[pos] = make_int2(s, __float_as_int(w));
}

// ---------------- prop, F=48: chunked-coalesced, fp16 neighbor gather ----------------
// thread t = node*6 + chunk; chunk = 8 halves (uint4) of the source row.
// mode=0: Tn = diag*Tc + gather ; mode=1: Tn = 2*(diag*Tc + gather) - Tp
__global__ __launch_bounds__(256)
void prop48_k(const float* __restrict__ Tc, const uint4* __restrict__ Tc16,
              const float* __restrict__ Tp, float* __restrict__ Tn,
              uint4* __restrict__ Tn16, int mode, int w16) {
    int t = blockIdx.x * blockDim.x + threadIdx.x;
    if (t >= NN * 6) return;
    int n = t / 6;
    int c = t - n * 6;            // uint4 chunk index: halves [8c, 8c+8)
    float dg = g_diag[n];
    const float4* crow = reinterpret_cast<const float4*>(Tc + n * 48 + c * 8);
    float4 v0 = __ldg(&crow[0]);
    float4 v1 = __ldg(&crow[1]);
    float a0 = dg * v0.x, a1 = dg * v0.y, a2 = dg * v0.z, a3 = dg * v0.w;
    float a4 = dg * v1.x, a5 = dg * v1.y, a6 = dg * v1.z, a7 = dg * v1.w;
    const int e1 = g_rowptr[n + 1];
#pragma unroll 2
    for (int j = g_rowptr[n]; j < e1; ++j) {
        int2 e = __ldg(&g_edge[j]);                 // broadcast across 6 lanes of node
        float w = __int_as_float(e.y);
        uint4 q = __ldg(&Tc16[(size_t)e.x * 6 + c]); // 6 lanes contiguous: 96B row
        float2 f0 = __half22float2(*reinterpret_cast<const __half2*>(&q.x));
        float2 f1 = __half22float2(*reinterpret_cast<const __half2*>(&q.y));
        float2 f2 = __half22float2(*reinterpret_cast<const __half2*>(&q.z));
        float2 f3 = __half22float2(*reinterpret_cast<const __half2*>(&q.w));
        a0 += w * f0.x; a1 += w * f0.y; a2 += w * f1.x; a3 += w * f1.y;
        a4 += w * f2.x; a5 += w * f2.y; a6 += w * f3.x; a7 += w * f3.y;
    }
    if (mode) {
        const float4* prow = reinterpret_cast<const float4*>(Tp + n * 48 + c * 8);
        float4 p0 = __ldg(&prow[0]);
        float4 p1 = __ldg(&prow[1]);
        a0 = 2.f * a0 - p0.x; a1 = 2.f * a1 - p0.y;
        a2 = 2.f * a2 - p0.z; a3 = 2.f * a3 - p0.w;
        a4 = 2.f * a4 - p1.x; a5 = 2.f * a5 - p1.y;
        a6 = 2.f * a6 - p1.z; a7 = 2.f * a7 - p1.w;
    }
    float4* orow = reinterpret_cast<float4*>(Tn + n * 48 + c * 8);
    orow[0] = make_float4(a0, a1, a2, a3);
    orow[1] = make_float4(a4, a5, a6, a7);
    if (w16) {
        __half2 h0 = __float22half2_rn(make_float2(a0, a1));
        __half2 h1 = __float22half2_rn(make_float2(a2, a3));
        __half2 h2 = __float22half2_rn(make_float2(a4, a5));
        __half2 h3 = __float22half2_rn(make_float2(a6, a7));
        uint4 q;
        q.x = *reinterpret_cast<unsigned*>(&h0);
        q.y = *reinterpret_cast<unsigned*>(&h1);
        q.z = *reinterpret_cast<unsigned*>(&h2);
        q.w = *reinterpret_cast<unsigned*>(&h3);
        Tn16[(size_t)n * 6 + c] = q;
    }
}

// ---------------- prop, F=16: chunked-coalesced fp32 (layer 1) ----------------
// thread t = node*4 + chunk; chunk = float4.
__global__ __launch_bounds__(256)
void prop16_k(const float4* __restrict__ Tc, const float4* __restrict__ Tp,
              float4* __restrict__ Tn, int mode) {
    int t = blockIdx.x * blockDim.x + threadIdx.x;
    if (t >= NN * 4) return;
    int n = t >> 2;
    float dg = g_diag[n];
    float4 v = __ldg(&Tc[t]);
    float a0 = dg * v.x, a1 = dg * v.y, a2 = dg * v.z, a3 = dg * v.w;
    int c = t & 3;
    const int e1 = g_rowptr[n + 1];
#pragma unroll 2
    for (int j = g_rowptr[n]; j < e1; ++j) {
        int2 e = __ldg(&g_edge[j]);              // broadcast across 4 lanes of node
        float w = __int_as_float(e.y);
        float4 q = __ldg(&Tc[e.x * 4 + c]);       // 4 lanes contiguous: 64B row
        a0 += w * q.x; a1 += w * q.y; a2 += w * q.z; a3 += w * q.w;
    }
    if (mode) {
        float4 p = __ldg(&Tp[t]);
        a0 = 2.f * a0 - p.x; a1 = 2.f * a1 - p.y;
        a2 = 2.f * a2 - p.z; a3 = 2.f * a3 - p.w;
    }
    Tn[t] = make_float4(a0, a1, a2, a3);
}

// ---------------- per-layer GEMM: H' = relu(sum_k T_k @ W[k] + b) ----------------
// tile: 256 nodes x 48 h, threads (32,6), thread = 8 nodes (stride 32) x 8 h
template <int F>
__device__ __forceinline__ void gemm_phase(const float* __restrict__ Tk,
                                           const float* __restrict__ Wsk,
                                           float* __restrict__ Ts,
                                           float acc[8][8], int n0, int tx, int ty, int tid) {
    const int PITCH = F + 1;
    __syncthreads();
    for (int idx = tid; idx < 256 * F; idx += 192) {
        int node = idx / F, f = idx - node * F;
        int gn = n0 + node;
        Ts[node * PITCH + f] = (gn < NN) ? Tk[(size_t)gn * F + f] : 0.f;
    }
    __syncthreads();
#pragma unroll 4
    for (int f = 0; f < F; ++f) {
        float4 w0 = *reinterpret_cast<const float4*>(&Wsk[f * 48 + ty * 8]);
        float4 w1 = *reinterpret_cast<const float4*>(&Wsk[f * 48 + ty * 8 + 4]);
#pragma unroll
        for (int i = 0; i < 8; ++i) {
            float t = Ts[(tx + 32 * i) * PITCH + f];
            acc[i][0] += t * w0.x; acc[i][1] += t * w0.y;
            acc[i][2] += t * w0.z; acc[i][3] += t * w0.w;
            acc[i][4] += t * w1.x; acc[i][5] += t * w1.y;
            acc[i][6] += t * w1.z; acc[i][7] += t * w1.w;
        }
    }
}

template <int F>
__global__ __launch_bounds__(192, 2)
void gemm5_k(const float* __restrict__ T0, const float* __restrict__ T1,
             const float* __restrict__ T2, const float* __restrict__ T3,
             const float* __restrict__ T4,
             const float* __restrict__ W, const float* __restrict__ bias,
             float* __restrict__ OUT, uint4* __restrict__ OUT16, int w16) {
    extern __shared__ float smem[];
    float* Ws = smem;                       // 5*F*48
    float* Ts = smem + 5 * F * 48;          // 256*(F+1)
    const int tx = threadIdx.x, ty = threadIdx.y;
    const int tid = ty * 32 + tx;
    const int n0 = blockIdx.x * 256;
    for (int i = tid; i < 5 * F * 48; i += 192) Ws[i] = W[i];
    float acc[8][8];
#pragma unroll
    for (int i = 0; i < 8; ++i)
#pragma unroll
        for (int j = 0; j < 8; ++j) acc[i][j] = 0.f;

    gemm_phase<F>(T0, Ws + 0 * F * 48, Ts, acc, n0, tx, ty, tid);
    gemm_phase<F>(T1, Ws + 1 * F * 48, Ts, acc, n0, tx, ty, tid);
    gemm_phase<F>(T2, Ws + 2 * F * 48, Ts, acc, n0, tx, ty, tid);
    gemm_phase<F>(T3, Ws + 3 * F * 48, Ts, acc, n0, tx, ty, tid);
    gemm_phase<F>(T4, Ws + 4 * F * 48, Ts, acc, n0, tx, ty, tid);

    float b[8];
#pragma unroll
    for (int j = 0; j < 8; ++j) b[j] = bias[ty * 8 + j];
#pragma unroll
    for (int i = 0; i < 8; ++i) {
        int n = n0 + tx + 32 * i;
        if (n >= NN) continue;
        float r[8];
#pragma unroll
        for (int j = 0; j < 8; ++j) r[j] = fmaxf(acc[i][j] + b[j], 0.f);
        float4* o = reinterpret_cast<float4*>(OUT + (size_t)n * 48 + ty * 8);
        o[0] = make_float4(r[0], r[1], r[2], r[3]);
        o[1] = make_float4(r[4], r[5], r[6], r[7]);
        if (w16) {
            __half2 h0 = __float22half2_rn(make_float2(r[0], r[1]));
            __half2 h1 = __float22half2_rn(make_float2(r[2], r[3]));
            __half2 h2 = __float22half2_rn(make_float2(r[4], r[5]));
            __half2 h3 = __float22half2_rn(make_float2(r[6], r[7]));
            uint4 q;
            q.x = *reinterpret_cast<unsigned*>(&h0);
            q.y = *reinterpret_cast<unsigned*>(&h1);
            q.z = *reinterpret_cast<unsigned*>(&h2);
            q.w = *reinterpret_cast<unsigned*>(&h3);
            OUT16[(size_t)n * 6 + ty] = q;
        }
    }
}

// ---------------- pooling ----------------
__global__ void pool_k(const float* __restrict__ Hin) {
    __shared__ float red[8][48];
    const int g = blockIdx.x;
    const int h = threadIdx.x;
    const int y = threadIdx.y;
    const float* base = Hin + (size_t)g * 1000 * 48;
    float s = 0.f;
    for (int i = y; i < 1000; i += 8) s += base[i * 48 + h];
    red[y][h] = s;
    __syncthreads();
    if (y == 0) {
        float t = 0.f;
#pragma unroll
        for (int q = 0; q < 8; ++q) t += red[q][h];
        g_pool[g * 48 + h] = t;
    }
}

__global__ void mlp_k(const float* __restrict__ fc1w, const float* __restrict__ fc1b,
                      const float* __restrict__ fc2w, const float* __restrict__ fc2b,
                      float* __restrict__ out) {
    const int g = blockIdx.x;
    const int j = threadIdx.x;
    float a = fc1b[j];
#pragma unroll
    for (int f = 0; f < 48; ++f) a += g_pool[g * 48 + f] * fc1w[f * 32 + j];
    a = fmaxf(a, 0.f);
    float v = a * fc2w[j];
#pragma unroll
    for (int off = 16; off; off >>= 1) v += __shfl_down_sync(0xffffffffu, v, off);
    if (j == 0) out[g] = v + fc2b[0];
}

extern "C" void kernel_launch(void* const* d_in, const int* in_sizes, int n_in,
                              void* d_out, int out_size) {
    (void)in_sizes; (void)n_in; (void)out_size;
    const float* x     = (const float*)d_in[0];
    const int*   ei    = (const int*)  d_in[1];
    const int*   batch = (const int*)  d_in[2];
    const float* lmax  = (const float*)d_in[3];
    const float* W1 = (const float*)d_in[4];  const float* b1 = (const float*)d_in[5];
    const float* W2 = (const float*)d_in[6];  const float* b2 = (const float*)d_in[7];
    const float* W3 = (const float*)d_in[8];  const float* b3 = (const float*)d_in[9];
    const float* W4 = (const float*)d_in[10]; const float* b4 = (const float*)d_in[11];
    const float* W5 = (const float*)d_in[12]; const float* b5 = (const float*)d_in[13];
    const float* fc1w = (const float*)d_in[14]; const float* fc1b = (const float*)d_in[15];
    const float* fc2w = (const float*)d_in[16]; const float* fc2b = (const float*)d_in[17];
    float* out = (float*)d_out;

    void* p;
    cudaGetSymbolAddress(&p, g_T1);   float* T1 = (float*)p;
    cudaGetSymbolAddress(&p, g_T2);   float* T2 = (float*)p;
    cudaGetSymbolAddress(&p, g_T3);   float* T3 = (float*)p;
    cudaGetSymbolAddress(&p, g_T4);   float* T4 = (float*)p;
    cudaGetSymbolAddress(&p, g_H);    float* Hb = (float*)p;
    cudaGetSymbolAddress(&p, g_H16);  uint4* H16 = (uint4*)p;
    cudaGetSymbolAddress(&p, g_T116); uint4* T116 = (uint4*)p;
    cudaGetSymbolAddress(&p, g_T216); uint4* T216 = (uint4*)p;
    cudaGetSymbolAddress(&p, g_T316); uint4* T316 = (uint4*)p;
    cudaGetSymbolAddress(&p, g_outc); void* outc_p = p;
    cudaGetSymbolAddress(&p, g_inc);  void* inc_p  = p;
    cudaGetSymbolAddress(&p, g_fill); void* fill_p = p;

    cudaMemsetAsync(outc_p, 0, NN * sizeof(int));
    cudaMemsetAsync(inc_p,  0, NN * sizeof(int));
    cudaMemsetAsync(fill_p, 0, NN * sizeof(int));

    const int EB = (EE + 255) / 256;
    deg_k<<<EB, 256>>>(ei);
    scan_k<<<1, 1024>>>();
    nodeinit_k<<<(NN + 255) / 256, 256>>>(batch, lmax);
    wedge_k<<<EB, 256>>>(ei, batch, lmax);

    const int smem48 = (5 * 48 * 48 + 256 * 49) * sizeof(float);
    const int smem16 = (5 * 16 * 48 + 256 * 17) * sizeof(float);
    cudaFuncSetAttribute(gemm5_k<48>, cudaFuncAttributeMaxDynamicSharedMemorySize, smem48);
    cudaFuncSetAttribute(gemm5_k<16>, cudaFuncAttributeMaxDynamicSharedMemorySize, smem16);

    const int GB = (NN + 255) / 256;
    dim3 gt(32, 6);
    const int PB48 = (NN * 6 + 255) / 256;   // prop48 grid (chunked)
    const int PB16 = (NN * 4 + 255) / 256;   // prop16 grid (chunked)

    // ---- layer 1 (F=16, fp32 chunked gather) ----
    const float4* x4 = (const float4*)x;
    prop16_k<<<PB16, 256>>>(x4, nullptr,        (float4*)T1, 0);
    prop16_k<<<PB16, 256>>>((const float4*)T1, x4,            (float4*)T2, 1);
    prop16_k<<<PB16, 256>>>((const float4*)T2, (const float4*)T1, (float4*)T3, 1);
    prop16_k<<<PB16, 256>>>((const float4*)T3, (const float4*)T2, (float4*)T4, 1);
    gemm5_k<16><<<GB, gt, smem16>>>(x, T1, T2, T3, T4, W1, b1, Hb, H16, 1);

    // ---- layers 2..5 (F=48, fp16 chunked gather) ----
    const float* Ws[4] = {W2, W3, W4, W5};
    const float* bs[4] = {b2, b3, b4, b5};
    for (int L = 0; L < 4; ++L) {
        prop48_k<<<PB48, 256>>>(Hb, H16,  nullptr, T1, T116, 0, 1);
        prop48_k<<<PB48, 256>>>(T1, T116, Hb,      T2, T216, 1, 1);
        prop48_k<<<PB48, 256>>>(T2, T216, T1,      T3, T316, 1, 1);
        prop48_k<<<PB48, 256>>>(T3, T316, T2,      T4, nullptr, 1, 0);
        int last = (L == 3);
        gemm5_k<48><<<GB, gt, smem48>>>(Hb, T1, T2, T3, T4, Ws[L], bs[L], Hb, H16, last ? 0 : 1);
    }

    pool_k<<<GG, dim3(48, 8)>>>(Hb);
    mlp_k<<<GG, 32>>>(fc1w, fc1b, fc2w, fc2b, out);
}